// round 13
// baseline (speedup 1.0000x reference)
#include <cuda_runtime.h>
#include <cuda_fp16.h>
#include <cstdint>

#define BATCH 4
#define TSEQ  4096

typedef unsigned int u32;

// ---------------- device globals (no alloc allowed) ----------------
// fp16, natural [b][t][32] layout. g_q pre-scaled by 32^-0.5 * log2(e).
__device__ __half g_q[BATCH * TSEQ * 32];
__device__ __half g_k[BATCH * TSEQ * 32];
__device__ __half g_v[BATCH * TSEQ * 32];
__device__ float  g_po[BATCH * 32 * 16 * 128 * 32];  // split partial O
__device__ float  g_pl[BATCH * 32 * 16 * 128];       // split partial l

static __device__ __forceinline__ u32 h2pack(float hi, float lo) {
    u32 d; asm("cvt.rn.f16x2.f32 %0, %1, %2;" : "=r"(d) : "f"(hi), "f"(lo)); return d;
}
static __device__ __forceinline__ u32 h2exp(u32 x) {
    u32 y; asm("ex2.approx.f16x2 %0, %1;" : "=r"(y) : "r"(x)); return y;
}
static __device__ __forceinline__ u32 smem_u32(const void* p) {
    u32 a;
    asm("{ .reg .u64 t; cvta.to.shared.u64 t, %1; cvt.u32.u64 %0, t; }"
        : "=r"(a) : "l"(p));
    return a;
}
static __device__ __forceinline__ void cpasync16(u32 saddr, const void* g) {
    asm volatile("cp.async.ca.shared.global [%0], [%1], 16;" :: "r"(saddr), "l"(g));
}
#define CP_COMMIT()  asm volatile("cp.async.commit_group;" ::: "memory")
#define CP_WAIT(n)   asm volatile("cp.async.wait_group %0;" :: "n"(n) : "memory")

// D += A*B  (m16n8k16, fp16 in, f32 accum)
static __device__ __forceinline__ void mma16(float* d, const u32* a, u32 b0, u32 b1) {
    asm volatile(
        "mma.sync.aligned.m16n8k16.row.col.f32.f16.f16.f32 "
        "{%0,%1,%2,%3}, {%4,%5,%6,%7}, {%8,%9}, {%0,%1,%2,%3};"
        : "+f"(d[0]), "+f"(d[1]), "+f"(d[2]), "+f"(d[3])
        : "r"(a[0]), "r"(a[1]), "r"(a[2]), "r"(a[3]), "r"(b0), "r"(b1));
}
static __device__ __forceinline__ void ldsm4(u32& r0, u32& r1, u32& r2, u32& r3, u32 a) {
    asm volatile("ldmatrix.sync.aligned.m8n8.x4.shared.b16 {%0,%1,%2,%3}, [%4];"
        : "=r"(r0), "=r"(r1), "=r"(r2), "=r"(r3) : "r"(a));
}
static __device__ __forceinline__ void ldsm4t(u32& r0, u32& r1, u32& r2, u32& r3, u32 a) {
    asm volatile("ldmatrix.sync.aligned.m8n8.x4.trans.shared.b16 {%0,%1,%2,%3}, [%4];"
        : "=r"(r0), "=r"(r1), "=r"(r2), "=r"(r3) : "r"(a));
}

// uniform 4-tile splits: qtile qi has n=2(qi+1) key tiles, s_i = ceil((qi+1)/2)
static __device__ __forceinline__ int nsplits(int i) { return (i + 2) >> 1; }

// ---------------------------------------------------------------------------
// Kernel 1: QKV projection on tensor cores. 512 CTAs x 32 rows, 256 threads.
// Warp = (row-group rg = w>>2, n-tile j = w&3): 16 rows x 1 n-tile x 3 mats.
// 4096 warps total (~28/SM) — occupancy fix for the gmem-latency stall.
// ---------------------------------------------------------------------------
__global__ __launch_bounds__(256) void qkv_kernel(
    const float* __restrict__ x,
    const float* __restrict__ Wq,
    const float* __restrict__ Wk,
    const float* __restrict__ Wv)
{
    __shared__ __align__(128) char sW[3][2048];   // [m][h*64B row, swizzled]

    int tid  = threadIdx.x;
    int lane = tid & 31;
    int w    = tid >> 5;
    int g    = lane >> 2;
    int t4   = lane & 3;
    int rg   = w >> 2;        // row group 0..1
    int j    = w & 3;         // n-tile 0..3

    // ---- stage W (first 128 threads): chunk (h = tid>>2, c = tid&3) ----
    if (tid < 128) {
        int h = tid >> 2, c = tid & 3;
        const float QS = 0.17677669529663687f * 1.4426950408889634f; // 32^-0.5*log2e
        const float* Ws[3] = { Wq, Wk, Wv };
        u32 off = (u32)(h * 64 + ((c ^ ((h >> 1) & 3)) << 4));
#pragma unroll
        for (int m = 0; m < 3; m++) {
            const float4* wp = (const float4*)(Ws[m] + h * 32 + c * 8);
            float4 w0 = wp[0], w1 = wp[1];
            float sc = (m == 0) ? QS : 1.0f;
            uint4 pk;
            pk.x = h2pack(w0.y * sc, w0.x * sc);
            pk.y = h2pack(w0.w * sc, w0.z * sc);
            pk.z = h2pack(w1.y * sc, w1.x * sc);
            pk.w = h2pack(w1.w * sc, w1.z * sc);
            *(uint4*)(sW[m] + off) = pk;
        }
    }

    // ---- A fragments: rows (rA, rA+8), fp32 x -> packed fp16 ----
    int rA = blockIdx.x * 32 + 16 * rg + g;
    u32 qa[2][4];
#pragma unroll
    for (int ks = 0; ks < 2; ks++) {
        const float* xA = x + (size_t)rA * 32 + 16 * ks;
        const float* xB = xA + 8 * 32;
        float2 f0 = *(const float2*)(xA + 2 * t4);
        float2 f1 = *(const float2*)(xB + 2 * t4);
        float2 f2 = *(const float2*)(xA + 2 * t4 + 8);
        float2 f3 = *(const float2*)(xB + 2 * t4 + 8);
        qa[ks][0] = h2pack(f0.y, f0.x);
        qa[ks][1] = h2pack(f1.y, f1.x);
        qa[ks][2] = h2pack(f2.y, f2.x);
        qa[ks][3] = h2pack(f3.y, f3.x);
    }
    __syncthreads();

    u32 wlm = (u32)((lane & 7) * 64 + ((((lane >> 3) ^ (((lane & 7) >> 1) & 3))) << 4));
    u32 sWb[3] = { smem_u32(sW[0]), smem_u32(sW[1]), smem_u32(sW[2]) };
    __half* dsts[3] = { g_q, g_k, g_v };

#pragma unroll
    for (int m = 0; m < 3; m++) {
        u32 b0, b1, b2, b3;
        ldsm4(b0, b1, b2, b3, sWb[m] + (u32)(j * 512) + wlm);
        float c[4] = {0.f, 0.f, 0.f, 0.f};
        mma16(c, qa[0], b0, b1);
        mma16(c, qa[1], b2, b3);
        int col = j * 8 + 2 * t4;
        *(u32*)(dsts[m] + (size_t)rA * 32 + col)       = h2pack(c[1], c[0]);
        *(u32*)(dsts[m] + (size_t)(rA + 8) * 32 + col) = h2pack(c[3], c[2]);
    }
}

// ---------------------------------------------------------------------------
// Kernel 2: fp16 m16n8k16 flash attention (no-max softmax, uniform split-KV).
// UNCHANGED from the 37.4us R11 baseline (f32-accum QK, packed exp, l=P·1).
// ---------------------------------------------------------------------------
__global__ __launch_bounds__(256, 3) void attn_kernel(float* __restrict__ out)
{
    __shared__ __align__(128) char sK[2][64 * 64];   // [key][dim] fp16, swizzled
    __shared__ __align__(128) char sV[2][64 * 64];

    int tid  = threadIdx.x;
    int lane = tid & 31;
    int w    = tid >> 5;
    int g    = lane >> 2;     // group id 0..7
    int t4   = lane & 3;      // thread in group
    int b    = blockIdx.y;

    // map blockIdx.x -> (qtile qi, split p)
    int u = blockIdx.x, qi = 0, s = 1;
    for (qi = 0; qi < 32; qi++) {
        s = nsplits(qi);
        if (u < s) break;
        u -= s;
    }
    int p  = u;
    int n  = 2 * (qi + 1);
    int tb = p * 4;
    int te = (tb + 4 < n) ? tb + 4 : n;
    int r0 = qi * 128;
    int rA = r0 + 16 * w + g;     // this lane's first q-row (second = rA+8)

    u32 sKb[2] = { smem_u32(&sK[0][0]), smem_u32(&sK[1][0]) };
    u32 sVb[2] = { smem_u32(&sV[0][0]), smem_u32(&sV[1][0]) };

    // cp.async staging offset (swizzle chunk ^ ((row>>1)&3))
    u32 stoff = (u32)((tid >> 2) * 64 + (((tid & 3) ^ ((tid >> 3) & 3)) << 4));
    // ldmatrix K address offset
    u32 klm = (u32)((lane & 7) * 64 + ((((lane >> 3) ^ (((lane & 7) >> 1) & 3))) << 4));
    // ldmatrix V lane mapping
    int vkey = (lane & 7) + 8 * ((lane >> 3) & 1);
    int vch  = (lane >> 4);

    // ones-column B fragment for l = P·1 (n==0 column all ones)
    u32 bl = (g == 0) ? 0x3C003C00u : 0u;

    // ---- Q fragments ----
    u32 qa[2][4];
    {
        const __half* qA = g_q + ((size_t)b * TSEQ + rA) * 32;
        const __half* qB = qA + 8 * 32;
#pragma unroll
        for (int ks = 0; ks < 2; ks++) {
            qa[ks][0] = *(const u32*)(qA + 16 * ks + 2 * t4);
            qa[ks][1] = *(const u32*)(qB + 16 * ks + 2 * t4);
            qa[ks][2] = *(const u32*)(qA + 16 * ks + 2 * t4 + 8);
            qa[ks][3] = *(const u32*)(qB + 16 * ks + 2 * t4 + 8);
        }
    }

    float oc[4][4];
#pragma unroll
    for (int jd = 0; jd < 4; jd++)
#pragma unroll
        for (int q = 0; q < 4; q++) oc[jd][q] = 0.f;
    float lc[4] = {0.f, 0.f, 0.f, 0.f};   // l accumulator (col 0 meaningful)

    // ---- stage tile tb into buffer 0 ----
    {
        const char* kg = (const char*)(g_k + ((size_t)b * TSEQ + tb * 64) * 32);
        const char* vg = (const char*)(g_v + ((size_t)b * TSEQ + tb * 64) * 32);
        u32 goff = (u32)((tid >> 2) * 64 + (tid & 3) * 16);
        cpasync16(sKb[0] + stoff, kg + goff);
        cpasync16(sVb[0] + stoff, vg + goff);
        CP_COMMIT();
    }

    int cur = 0;

    for (int t = tb; t < te; t++) {
        bool havenext = (t + 1 < te);
        if (havenext) {
            const char* kg = (const char*)(g_k + ((size_t)b * TSEQ + (t + 1) * 64) * 32);
            const char* vg = (const char*)(g_v + ((size_t)b * TSEQ + (t + 1) * 64) * 32);
            u32 goff = (u32)((tid >> 2) * 64 + (tid & 3) * 16);
            cpasync16(sKb[cur ^ 1] + stoff, kg + goff);
            cpasync16(sVb[cur ^ 1] + stoff, vg + goff);
            CP_COMMIT();
            CP_WAIT(1);
        } else {
            CP_WAIT(0);
        }
        __syncthreads();

        u32 cK = sKb[cur];
        u32 cV = sVb[cur];
        bool domask = (t >= 2 * qi);

        u32 pp01 = 0, pp23 = 0;   // packed scores of even chunk, pending PV

#pragma unroll
        for (int j = 0; j < 8; j++) {
            // ---- K frags: one ldmatrix.x4 per 8-key chunk ----
            u32 kb0, kb1, kb2, kb3;
            ldsm4(kb0, kb1, kb2, kb3, cK + (u32)(j * 512) + klm);

            float sa[4] = {0.f, 0.f, 0.f, 0.f};
            mma16(sa, qa[0], kb0, kb1);
            mma16(sa, qa[1], kb2, kb3);

            // ---- mask (pre-exp) + pack to fp16 pairs ----
            int ct = t * 64 + 8 * j + 2 * t4;
            if (domask) {
                if (ct     > rA)     sa[0] = -1e30f;   // -> fp16 -inf -> exp 0
                if (ct + 1 > rA)     sa[1] = -1e30f;
                if (ct     > rA + 8) sa[2] = -1e30f;
                if (ct + 1 > rA + 8) sa[3] = -1e30f;
            }
            u32 p01 = h2pack(sa[1], sa[0]);
            u32 p23 = h2pack(sa[3], sa[2]);

            if ((j & 1) == 0) {
                pp01 = p01; pp23 = p23;
            } else {
                // ---- packed exp: P frags for the 16-key group c = j>>1 ----
                u32 pa[4];
                pa[0] = h2exp(pp01);
                pa[1] = h2exp(pp23);
                pa[2] = h2exp(p01);
                pa[3] = h2exp(p23);
                int c = j >> 1;
#pragma unroll
                for (int pr = 0; pr < 2; pr++) {
                    u32 vb0, vb1, vb2, vb3;
                    int key = c * 16 + vkey;
                    int ch  = 2 * pr + vch;
                    u32 va = cV + (u32)(key * 64 + ((ch ^ ((key >> 1) & 3)) << 4));
                    ldsm4t(vb0, vb1, vb2, vb3, va);
                    mma16(oc[2 * pr],     pa, vb0, vb1);
                    mma16(oc[2 * pr + 1], pa, vb2, vb3);
                }
                mma16(lc, pa, bl, bl);       // l += P · ones-column
            }
        }

        __syncthreads();
        cur ^= 1;
    }

    // ---- extract row sums: l lives in col 0 (t4==0 lanes), c0/c2 ----
    float ls0 = __shfl_sync(0xffffffffu, lc[0], lane & ~3);
    float ls1 = __shfl_sync(0xffffffffu, lc[2], lane & ~3);

    // ---- epilogue ----
    if (s == 1) {
        float i0 = 1.0f / ls0;
        float i1 = 1.0f / ls1;
        float* oA = out + ((size_t)b * TSEQ + rA) * 32;
        float* oB = oA + 8 * 32;
#pragma unroll
        for (int jd = 0; jd < 4; jd++) {
            *(float2*)&oA[8 * jd + 2 * t4] = make_float2(oc[jd][0] * i0, oc[jd][1] * i0);
            *(float2*)&oB[8 * jd + 2 * t4] = make_float2(oc[jd][2] * i1, oc[jd][3] * i1);
        }
    } else {
        size_t base = ((size_t)(b * 32 + qi) * 16 + p) * 128;
        int lr = 16 * w + g;
        float* pA = g_po + (base + lr) * 32;
        float* pB = pA + 8 * 32;
#pragma unroll
        for (int jd = 0; jd < 4; jd++) {
            *(float2*)&pA[8 * jd + 2 * t4] = make_float2(oc[jd][0], oc[jd][1]);
            *(float2*)&pB[8 * jd + 2 * t4] = make_float2(oc[jd][2], oc[jd][3]);
        }
        if (t4 == 0) {
            g_pl[base + lr]     = ls0;
            g_pl[base + lr + 8] = ls1;
        }
    }
}

// ---------------------------------------------------------------------------
// Kernel 3: combine split partials: out = sum_p O_p / sum_p l_p
// ---------------------------------------------------------------------------
__global__ __launch_bounds__(128) void combine_kernel(float* __restrict__ out)
{
    int qi = blockIdx.x, b = blockIdx.y, r = threadIdx.x;
    int s = nsplits(qi);
    if (s < 2) return;

    float l = 0.f;
    for (int p = 0; p < s; p++)
        l += g_pl[((size_t)(b * 32 + qi) * 16 + p) * 128 + r];
    float inv = 1.0f / l;

    float4 o[8];
#pragma unroll
    for (int j = 0; j < 8; j++) o[j] = make_float4(0.f, 0.f, 0.f, 0.f);
    for (int p = 0; p < s; p++) {
        const float4* pp = (const float4*)(g_po +
            (((size_t)(b * 32 + qi) * 16 + p) * 128 + r) * 32);
#pragma unroll
        for (int j = 0; j < 8; j++) {
            float4 a = pp[j];
            o[j].x += a.x; o[j].y += a.y; o[j].z += a.z; o[j].w += a.w;
        }
    }
    float4* op = (float4*)(out + ((size_t)b * TSEQ + qi * 128 + r) * 32);
#pragma unroll
    for (int j = 0; j < 8; j++) {
        o[j].x *= inv; o[j].y *= inv; o[j].z *= inv; o[j].w *= inv;
        op[j] = o[j];
    }
}

// ---------------------------------------------------------------------------
extern "C" void kernel_launch(void* const* d_in, const int* in_sizes, int n_in,
                              void* d_out, int out_size)
{
    const float* x  = (const float*)d_in[0];
    const float* Wq = (const float*)d_in[1];
    const float* Wk = (const float*)d_in[2];
    const float* Wv = (const float*)d_in[3];
    float* out = (float*)d_out;

    qkv_kernel<<<(BATCH * TSEQ) / 32, 256>>>(x, Wq, Wk, Wv);

    dim3 grid(272, BATCH);              // sum_i ceil((i+1)/2) = 272 per batch
    attn_kernel<<<grid, 256>>>(out);

    combine_kernel<<<dim3(32, BATCH), 128>>>(out);
}

// round 14
// speedup vs baseline: 1.0417x; 1.0417x over previous
#include <cuda_runtime.h>
#include <cuda_fp16.h>
#include <cstdint>

#define BATCH 4
#define TSEQ  4096

typedef unsigned int u32;

// ---------------- device globals (no alloc allowed) ----------------
// fp16, natural [b][t][32] layout. g_q pre-scaled by 32^-0.5 * log2(e).
__device__ __half g_q[BATCH * TSEQ * 32];
__device__ __half g_k[BATCH * TSEQ * 32];
__device__ __half g_v[BATCH * TSEQ * 32];
__device__ float  g_po[BATCH * 32 * 16 * 128 * 32];  // split partial O
__device__ float  g_pl[BATCH * 32 * 16 * 128];       // split partial l

static __device__ __forceinline__ u32 h2pack(float hi, float lo) {
    u32 d; asm("cvt.rn.f16x2.f32 %0, %1, %2;" : "=r"(d) : "f"(hi), "f"(lo)); return d;
}
static __device__ __forceinline__ u32 h2exp(u32 x) {
    u32 y; asm("ex2.approx.f16x2 %0, %1;" : "=r"(y) : "r"(x)); return y;
}
static __device__ __forceinline__ u32 smem_u32(const void* p) {
    u32 a;
    asm("{ .reg .u64 t; cvta.to.shared.u64 t, %1; cvt.u32.u64 %0, t; }"
        : "=r"(a) : "l"(p));
    return a;
}
static __device__ __forceinline__ void cpasync16(u32 saddr, const void* g) {
    asm volatile("cp.async.ca.shared.global [%0], [%1], 16;" :: "r"(saddr), "l"(g));
}
#define CP_COMMIT()  asm volatile("cp.async.commit_group;" ::: "memory")
#define CP_WAIT(n)   asm volatile("cp.async.wait_group %0;" :: "n"(n) : "memory")

// D += A*B  (m16n8k16, fp16 in, f32 accum)
static __device__ __forceinline__ void mma16(float* d, const u32* a, u32 b0, u32 b1) {
    asm volatile(
        "mma.sync.aligned.m16n8k16.row.col.f32.f16.f16.f32 "
        "{%0,%1,%2,%3}, {%4,%5,%6,%7}, {%8,%9}, {%0,%1,%2,%3};"
        : "+f"(d[0]), "+f"(d[1]), "+f"(d[2]), "+f"(d[3])
        : "r"(a[0]), "r"(a[1]), "r"(a[2]), "r"(a[3]), "r"(b0), "r"(b1));
}
static __device__ __forceinline__ void ldsm4(u32& r0, u32& r1, u32& r2, u32& r3, u32 a) {
    asm volatile("ldmatrix.sync.aligned.m8n8.x4.shared.b16 {%0,%1,%2,%3}, [%4];"
        : "=r"(r0), "=r"(r1), "=r"(r2), "=r"(r3) : "r"(a));
}
static __device__ __forceinline__ void ldsm4t(u32& r0, u32& r1, u32& r2, u32& r3, u32 a) {
    asm volatile("ldmatrix.sync.aligned.m8n8.x4.trans.shared.b16 {%0,%1,%2,%3}, [%4];"
        : "=r"(r0), "=r"(r1), "=r"(r2), "=r"(r3) : "r"(a));
}

// uniform splits: qtile qi has (qi+1) 128-key tiles, 2 per split CTA
static __device__ __forceinline__ int nsplits(int i) { return (i + 2) >> 1; }

// ---------------------------------------------------------------------------
// Kernel 1: QKV projection on tensor cores (R11 version: 256 CTAs x 64 rows,
// 128 threads; warp = 16 rows x 4 n-tiles x 3 matrices).
// ---------------------------------------------------------------------------
__global__ __launch_bounds__(128) void qkv_kernel(
    const float* __restrict__ x,
    const float* __restrict__ Wq,
    const float* __restrict__ Wk,
    const float* __restrict__ Wv)
{
    __shared__ __align__(128) char sW[3][2048];   // [m][h*64B row, swizzled]

    int tid  = threadIdx.x;
    int lane = tid & 31;
    int w    = tid >> 5;
    int g    = lane >> 2;
    int t4   = lane & 3;

    // ---- stage W: thread handles chunk (h = tid>>2, c = tid&3) of each matrix
    {
        int h = tid >> 2, c = tid & 3;
        const float QS = 0.17677669529663687f * 1.4426950408889634f; // 32^-0.5*log2e
        const float* Ws[3] = { Wq, Wk, Wv };
        u32 off = (u32)(h * 64 + ((c ^ ((h >> 1) & 3)) << 4));
#pragma unroll
        for (int m = 0; m < 3; m++) {
            const float4* wp = (const float4*)(Ws[m] + h * 32 + c * 8);
            float4 w0 = wp[0], w1 = wp[1];
            float sc = (m == 0) ? QS : 1.0f;
            uint4 pk;
            pk.x = h2pack(w0.y * sc, w0.x * sc);
            pk.y = h2pack(w0.w * sc, w0.z * sc);
            pk.z = h2pack(w1.y * sc, w1.x * sc);
            pk.w = h2pack(w1.w * sc, w1.z * sc);
            *(uint4*)(sW[m] + off) = pk;
        }
    }

    // ---- A fragments: rows (rA, rA+8), fp32 x -> packed fp16 ----
    int rA = blockIdx.x * 64 + 16 * w + g;
    u32 qa[2][4];
#pragma unroll
    for (int ks = 0; ks < 2; ks++) {
        const float* xA = x + (size_t)rA * 32 + 16 * ks;
        const float* xB = xA + 8 * 32;
        float2 f0 = *(const float2*)(xA + 2 * t4);
        float2 f1 = *(const float2*)(xB + 2 * t4);
        float2 f2 = *(const float2*)(xA + 2 * t4 + 8);
        float2 f3 = *(const float2*)(xB + 2 * t4 + 8);
        qa[ks][0] = h2pack(f0.y, f0.x);
        qa[ks][1] = h2pack(f1.y, f1.x);
        qa[ks][2] = h2pack(f2.y, f2.x);
        qa[ks][3] = h2pack(f3.y, f3.x);
    }
    __syncthreads();

    u32 wlm = (u32)((lane & 7) * 64 + ((((lane >> 3) ^ (((lane & 7) >> 1) & 3))) << 4));
    u32 sWb[3] = { smem_u32(sW[0]), smem_u32(sW[1]), smem_u32(sW[2]) };
    __half* dsts[3] = { g_q, g_k, g_v };

#pragma unroll
    for (int m = 0; m < 3; m++) {
        __half* dst = dsts[m];
#pragma unroll
        for (int j = 0; j < 4; j++) {       // n-tile: outputs h = 8j..8j+7
            u32 b0, b1, b2, b3;
            ldsm4(b0, b1, b2, b3, sWb[m] + (u32)(j * 512) + wlm);
            float c[4] = {0.f, 0.f, 0.f, 0.f};
            mma16(c, qa[0], b0, b1);
            mma16(c, qa[1], b2, b3);
            int col = j * 8 + 2 * t4;
            *(u32*)(dst + (size_t)rA * 32 + col)       = h2pack(c[1], c[0]);
            *(u32*)(dst + (size_t)(rA + 8) * 32 + col) = h2pack(c[3], c[2]);
        }
    }
}

// ---------------------------------------------------------------------------
// Kernel 2: fp16 m16n8k16 flash attention (no-max softmax, uniform split-KV).
// 128-KEY tiles (halved barrier count vs 64-key), double-buffered cp.async.
// ---------------------------------------------------------------------------
__global__ __launch_bounds__(256, 3) void attn_kernel(float* __restrict__ out)
{
    __shared__ __align__(128) char sK[2][128 * 64];  // [key][dim] fp16, swizzled
    __shared__ __align__(128) char sV[2][128 * 64];

    int tid  = threadIdx.x;
    int lane = tid & 31;
    int w    = tid >> 5;
    int g    = lane >> 2;     // group id 0..7
    int t4   = lane & 3;      // thread in group
    int b    = blockIdx.y;

    // map blockIdx.x -> (qtile qi, split p)
    int u = blockIdx.x, qi = 0, s = 1;
    for (qi = 0; qi < 32; qi++) {
        s = nsplits(qi);
        if (u < s) break;
        u -= s;
    }
    int p  = u;
    int n  = qi + 1;              // 128-key tiles covering the causal prefix
    int tb = p * 2;
    int te = (tb + 2 < n) ? tb + 2 : n;
    int r0 = qi * 128;
    int rA = r0 + 16 * w + g;     // this lane's first q-row (second = rA+8)

    u32 sKb[2] = { smem_u32(&sK[0][0]), smem_u32(&sK[1][0]) };
    u32 sVb[2] = { smem_u32(&sV[0][0]), smem_u32(&sV[1][0]) };

    // cp.async staging offset (swizzle chunk ^ ((row>>1)&3)); +4096 for 2nd half
    u32 stoff = (u32)((tid >> 2) * 64 + (((tid & 3) ^ ((tid >> 3) & 3)) << 4));
    u32 goff  = (u32)((tid >> 2) * 64 + (tid & 3) * 16);
    // ldmatrix K address offset
    u32 klm = (u32)((lane & 7) * 64 + ((((lane >> 3) ^ (((lane & 7) >> 1) & 3))) << 4));
    // ldmatrix V lane mapping
    int vkey = (lane & 7) + 8 * ((lane >> 3) & 1);
    int vch  = (lane >> 4);

    // ones-column B fragment for l = P·1 (n==0 column all ones)
    u32 bl = (g == 0) ? 0x3C003C00u : 0u;

    // ---- Q fragments ----
    u32 qa[2][4];
    {
        const __half* qA = g_q + ((size_t)b * TSEQ + rA) * 32;
        const __half* qB = qA + 8 * 32;
#pragma unroll
        for (int ks = 0; ks < 2; ks++) {
            qa[ks][0] = *(const u32*)(qA + 16 * ks + 2 * t4);
            qa[ks][1] = *(const u32*)(qB + 16 * ks + 2 * t4);
            qa[ks][2] = *(const u32*)(qA + 16 * ks + 2 * t4 + 8);
            qa[ks][3] = *(const u32*)(qB + 16 * ks + 2 * t4 + 8);
        }
    }

    float oc[4][4];
#pragma unroll
    for (int jd = 0; jd < 4; jd++)
#pragma unroll
        for (int q = 0; q < 4; q++) oc[jd][q] = 0.f;
    float lc[4] = {0.f, 0.f, 0.f, 0.f};   // l accumulator (col 0 meaningful)

    // ---- stage tile tb into buffer 0 (128 keys = 8KB K + 8KB V) ----
    {
        const char* kg = (const char*)(g_k + ((size_t)b * TSEQ + tb * 128) * 32);
        const char* vg = (const char*)(g_v + ((size_t)b * TSEQ + tb * 128) * 32);
        cpasync16(sKb[0] + stoff,        kg + goff);
        cpasync16(sKb[0] + stoff + 4096, kg + goff + 4096);
        cpasync16(sVb[0] + stoff,        vg + goff);
        cpasync16(sVb[0] + stoff + 4096, vg + goff + 4096);
        CP_COMMIT();
    }

    int cur = 0;

    for (int t = tb; t < te; t++) {
        bool havenext = (t + 1 < te);
        if (havenext) {
            const char* kg = (const char*)(g_k + ((size_t)b * TSEQ + (t + 1) * 128) * 32);
            const char* vg = (const char*)(g_v + ((size_t)b * TSEQ + (t + 1) * 128) * 32);
            cpasync16(sKb[cur ^ 1] + stoff,        kg + goff);
            cpasync16(sKb[cur ^ 1] + stoff + 4096, kg + goff + 4096);
            cpasync16(sVb[cur ^ 1] + stoff,        vg + goff);
            cpasync16(sVb[cur ^ 1] + stoff + 4096, vg + goff + 4096);
            CP_COMMIT();
            CP_WAIT(1);
        } else {
            CP_WAIT(0);
        }
        __syncthreads();

        u32 cK = sKb[cur];
        u32 cV = sVb[cur];
        bool domask = (t == qi);        // key tile == q tile size

        u32 pp01 = 0, pp23 = 0;   // packed scores of even chunk, pending PV

#pragma unroll
        for (int j = 0; j < 16; j++) {
            // ---- K frags: one ldmatrix.x4 per 8-key chunk ----
            u32 kb0, kb1, kb2, kb3;
            ldsm4(kb0, kb1, kb2, kb3, cK + (u32)(j * 512) + klm);

            float sa[4] = {0.f, 0.f, 0.f, 0.f};
            mma16(sa, qa[0], kb0, kb1);
            mma16(sa, qa[1], kb2, kb3);

            // ---- mask (pre-exp) + pack to fp16 pairs ----
            int ct = t * 128 + 8 * j + 2 * t4;
            if (domask) {
                if (ct     > rA)     sa[0] = -1e30f;   // -> fp16 -inf -> exp 0
                if (ct + 1 > rA)     sa[1] = -1e30f;
                if (ct     > rA + 8) sa[2] = -1e30f;
                if (ct + 1 > rA + 8) sa[3] = -1e30f;
            }
            u32 p01 = h2pack(sa[1], sa[0]);
            u32 p23 = h2pack(sa[3], sa[2]);

            if ((j & 1) == 0) {
                pp01 = p01; pp23 = p23;
            } else {
                // ---- packed exp: P frags for the 16-key group c = j>>1 ----
                u32 pa[4];
                pa[0] = h2exp(pp01);
                pa[1] = h2exp(pp23);
                pa[2] = h2exp(p01);
                pa[3] = h2exp(p23);
                int c = j >> 1;
#pragma unroll
                for (int pr = 0; pr < 2; pr++) {
                    u32 vb0, vb1, vb2, vb3;
                    int key = c * 16 + vkey;
                    int ch  = 2 * pr + vch;
                    u32 va = cV + (u32)(key * 64 + ((ch ^ ((key >> 1) & 3)) << 4));
                    ldsm4t(vb0, vb1, vb2, vb3, va);
                    mma16(oc[2 * pr],     pa, vb0, vb1);
                    mma16(oc[2 * pr + 1], pa, vb2, vb3);
                }
                mma16(lc, pa, bl, bl);       // l += P · ones-column
            }
        }

        __syncthreads();
        cur ^= 1;
    }

    // ---- extract row sums: l lives in col 0 (t4==0 lanes), c0/c2 ----
    float ls0 = __shfl_sync(0xffffffffu, lc[0], lane & ~3);
    float ls1 = __shfl_sync(0xffffffffu, lc[2], lane & ~3);

    // ---- epilogue ----
    if (s == 1) {
        float i0 = 1.0f / ls0;
        float i1 = 1.0f / ls1;
        float* oA = out + ((size_t)b * TSEQ + rA) * 32;
        float* oB = oA + 8 * 32;
#pragma unroll
        for (int jd = 0; jd < 4; jd++) {
            *(float2*)&oA[8 * jd + 2 * t4] = make_float2(oc[jd][0] * i0, oc[jd][1] * i0);
            *(float2*)&oB[8 * jd + 2 * t4] = make_float2(oc[jd][2] * i1, oc[jd][3] * i1);
        }
    } else {
        size_t base = ((size_t)(b * 32 + qi) * 16 + p) * 128;
        int lr = 16 * w + g;
        float* pA = g_po + (base + lr) * 32;
        float* pB = pA + 8 * 32;
#pragma unroll
        for (int jd = 0; jd < 4; jd++) {
            *(float2*)&pA[8 * jd + 2 * t4] = make_float2(oc[jd][0], oc[jd][1]);
            *(float2*)&pB[8 * jd + 2 * t4] = make_float2(oc[jd][2], oc[jd][3]);
        }
        if (t4 == 0) {
            g_pl[base + lr]     = ls0;
            g_pl[base + lr + 8] = ls1;
        }
    }
}

// ---------------------------------------------------------------------------
// Kernel 3: combine split partials: out = sum_p O_p / sum_p l_p
// ---------------------------------------------------------------------------
__global__ __launch_bounds__(128) void combine_kernel(float* __restrict__ out)
{
    int qi = blockIdx.x, b = blockIdx.y, r = threadIdx.x;
    int s = nsplits(qi);
    if (s < 2) return;

    float l = 0.f;
    for (int p = 0; p < s; p++)
        l += g_pl[((size_t)(b * 32 + qi) * 16 + p) * 128 + r];
    float inv = 1.0f / l;

    float4 o[8];
#pragma unroll
    for (int j = 0; j < 8; j++) o[j] = make_float4(0.f, 0.f, 0.f, 0.f);
    for (int p = 0; p < s; p++) {
        const float4* pp = (const float4*)(g_po +
            (((size_t)(b * 32 + qi) * 16 + p) * 128 + r) * 32);
#pragma unroll
        for (int j = 0; j < 8; j++) {
            float4 a = pp[j];
            o[j].x += a.x; o[j].y += a.y; o[j].z += a.z; o[j].w += a.w;
        }
    }
    float4* op = (float4*)(out + ((size_t)b * TSEQ + qi * 128 + r) * 32);
#pragma unroll
    for (int j = 0; j < 8; j++) {
        o[j].x *= inv; o[j].y *= inv; o[j].z *= inv; o[j].w *= inv;
        op[j] = o[j];
    }
}

// ---------------------------------------------------------------------------
extern "C" void kernel_launch(void* const* d_in, const int* in_sizes, int n_in,
                              void* d_out, int out_size)
{
    const float* x  = (const float*)d_in[0];
    const float* Wq = (const float*)d_in[1];
    const float* Wk = (const float*)d_in[2];
    const float* Wv = (const float*)d_in[3];
    float* out = (float*)d_out;

    qkv_kernel<<<(BATCH * TSEQ) / 64, 128>>>(x, Wq, Wk, Wv);

    dim3 grid(272, BATCH);              // sum_i ceil((i+1)/2) = 272 per batch
    attn_kernel<<<grid, 256>>>(out);

    combine_kernel<<<dim3(32, BATCH), 128>>>(out);
}